// round 4
// baseline (speedup 1.0000x reference)
#include <cuda_runtime.h>

#define IMG_H 512
#define IMG_W 512

#define LUT_N   8192
#define LUT_VLO (-6.0f)
#define LUT_VHI (8.0f)

__constant__ float c_k[9];
__device__ float d_lut[LUT_N];

// ---------- LUT build: exact act(v) on a uniform grid over [VLO, VHI] -------
__global__ void build_lut_kernel(const float* __restrict__ w1,
                                 const float* __restrict__ b1,
                                 const float* __restrict__ w2) {
    int i = blockIdx.x * blockDim.x + threadIdx.x;
    if (i >= LUT_N) return;
    float v = LUT_VLO + (LUT_VHI - LUT_VLO) * ((float)i / (float)(LUT_N - 1));
    float t = v - 1.0f;
    float g = expf(-t * t);                 // precise exp for table build
    float s = 0.0f;
#pragma unroll
    for (int j = 0; j < 10; ++j) {
        float h = fmaf(w1[j], g, b1[j]);
        s = fmaf(w2[j], fmaxf(h, 0.0f), s);
    }
    float sig = 1.0f / (1.0f + expf(-s));   // precise division
    d_lut[i] = sig - 0.5f;
}

// ---------- One NCA step: conv3x3 + LUT-lerp pointwise + residual -----------
template <int T>
__global__ __launch_bounds__(256) void step_kernel(const float* __restrict__ in,
                                                   float* __restrict__ out) {
    __shared__ float s_lut[LUT_N];
    {
        // cooperative copy: 8192 floats / 256 threads = 8 float4 each
        const int tid = threadIdx.y * 32 + threadIdx.x;
        const float4* src4 = reinterpret_cast<const float4*>(d_lut);
        float4* dst4 = reinterpret_cast<float4*>(s_lut);
#pragma unroll
        for (int i = 0; i < LUT_N / 4 / 256; ++i)
            dst4[tid + i * 256] = src4[tid + i * 256];
    }
    __syncthreads();

    const float inv_dv = (float)(LUT_N - 1) / (LUT_VHI - LUT_VLO);
    const float pmax   = (float)(LUT_N - 1) - 1.0e-3f;

    const int tx = threadIdx.x;                       // 0..31
    const int c0 = (blockIdx.x * 32 + tx) * 4;        // column of this thread's float4
    const int b  = blockIdx.z;
    const int y0 = (blockIdx.y * blockDim.y + threadIdx.y) * T;

    const float* img  = in  + (size_t)b * (IMG_H * IMG_W);
    float*       oimg = out + (size_t)b * (IMG_H * IMG_W);

    float win[3][6];   // 3-row sliding window, 6 cols: [c0-1, c0..c0+3, c0+4]

    auto load_row = [&](int y, float* r) {
#pragma unroll
        for (int i = 0; i < 6; ++i) r[i] = 0.0f;
        if (y >= 0 && y < IMG_H) {
            const float* p = img + y * IMG_W + c0;
            float4 v = *reinterpret_cast<const float4*>(p);
            r[1] = v.x; r[2] = v.y; r[3] = v.z; r[4] = v.w;
            if (c0 > 0)           r[0] = __ldg(p - 1);
            if (c0 + 4 < IMG_W)   r[5] = __ldg(p + 4);
        }
    };

    load_row(y0 - 1, win[0]);
    load_row(y0,     win[1]);

#pragma unroll
    for (int t = 0; t < T; ++t) {
        const int y = y0 + t;
        float* rm = win[(t + 0) % 3];   // row y-1
        float* rc = win[(t + 1) % 3];   // row y
        float* rp = win[(t + 2) % 3];   // row y+1
        load_row(y + 1, rp);

        float res[4];
#pragma unroll
        for (int i = 0; i < 4; ++i) {
            float v;
            v = c_k[0] * rm[i];
            v = fmaf(c_k[1], rm[i + 1], v);
            v = fmaf(c_k[2], rm[i + 2], v);
            v = fmaf(c_k[3], rc[i],     v);
            v = fmaf(c_k[4], rc[i + 1], v);
            v = fmaf(c_k[5], rc[i + 2], v);
            v = fmaf(c_k[6], rp[i],     v);
            v = fmaf(c_k[7], rp[i + 1], v);
            v = fmaf(c_k[8], rp[i + 2], v);
            // LUT lookup with linear interpolation (act is constant outside range)
            float p  = (v - LUT_VLO) * inv_dv;
            p = fminf(fmaxf(p, 0.0f), pmax);
            int   ip = __float2int_rd(p);
            float fr = p - (float)ip;
            float a0 = s_lut[ip];
            float a1 = s_lut[ip + 1];
            res[i] = rc[i + 1] + fmaf(a1 - a0, fr, a0);   // residual update
        }
        float4 o;
        o.x = res[0]; o.y = res[1]; o.z = res[2]; o.w = res[3];
        *reinterpret_cast<float4*>(oimg + y * IMG_W + c0) = o;
    }
}

extern "C" void kernel_launch(void* const* d_in, const int* in_sizes, int n_in,
                              void* d_out, int out_size) {
    const float* x  = (const float*)d_in[0];
    const float* k  = (const float*)d_in[1];
    const float* w1 = (const float*)d_in[2];
    const float* b1 = (const float*)d_in[3];
    const float* w2 = (const float*)d_in[4];
    float* out = (float*)d_out;

    const int npix  = in_sizes[0];                 // B*1*H*W
    const int B     = npix / (IMG_H * IMG_W);
    const int steps = out_size / npix - 1;

    // Conv weights -> constant memory (device-to-device async copy: capturable)
    cudaMemcpyToSymbolAsync(c_k, k, 9 * sizeof(float), 0, cudaMemcpyDeviceToDevice, 0);

    // Build the pointwise-activation LUT (reads MLP weights directly)
    build_lut_kernel<<<LUT_N / 256, 256>>>(w1, b1, w2);

    // Slice 0 of the output is the initial state
    cudaMemcpyAsync(out, x, (size_t)npix * sizeof(float), cudaMemcpyDeviceToDevice, 0);

    constexpr int T = 4;
    dim3 blk(32, 8, 1);
    dim3 grd(IMG_W / (32 * 4), IMG_H / (8 * T), B);   // (4, 16, B)

    for (int s = 0; s < steps; ++s) {
        const float* src = out + (size_t)s       * npix;
        float*       dst = out + (size_t)(s + 1) * npix;
        step_kernel<T><<<grd, blk>>>(src, dst);
    }
}

// round 5
// speedup vs baseline: 1.1724x; 1.1724x over previous
#include <cuda_runtime.h>

#define IMG_H 512
#define IMG_W 512

#define LUT_N   4096
#define LUT_VLO (-6.0f)
#define LUT_VHI (8.0f)

__constant__ float c_k[9];
__device__ float2 d_lut[LUT_N];   // {value, slope-to-next}

// exact pointwise chain for table build
__device__ float act_exact(float v, const float* w1, const float* b1, const float* w2) {
    float t = v - 1.0f;
    float g = expf(-t * t);
    float s = 0.0f;
#pragma unroll
    for (int j = 0; j < 10; ++j) {
        float h = fmaf(w1[j], g, b1[j]);
        s = fmaf(w2[j], fmaxf(h, 0.0f), s);
    }
    return 1.0f / (1.0f + expf(-s)) - 0.5f;
}

__global__ void build_lut_kernel(const float* __restrict__ w1,
                                 const float* __restrict__ b1,
                                 const float* __restrict__ w2) {
    int i = blockIdx.x * blockDim.x + threadIdx.x;
    if (i >= LUT_N) return;
    const float dv = (LUT_VHI - LUT_VLO) / (float)(LUT_N - 1);
    float v0 = LUT_VLO + dv * (float)i;
    float f0 = act_exact(v0, w1, b1, w2);
    float sl = 0.0f;
    if (i < LUT_N - 1) {
        float f1 = act_exact(v0 + dv, w1, b1, w2);
        sl = f1 - f0;
    }
    d_lut[i] = make_float2(f0, sl);
}

// One NCA step: conv3x3 -> LUT lerp -> residual.
// blockDim=(32,8); each thread: 4 cols (float4) x T rows, sliding 3-row window.
template <int T>
__global__ __launch_bounds__(256) void step_kernel(const float* __restrict__ in,
                                                   float* __restrict__ out) {
    __shared__ float2 s_lut[LUT_N];
    {
        const int tid = threadIdx.y * 32 + threadIdx.x;
        const float4* src4 = reinterpret_cast<const float4*>(d_lut);
        float4* dst4 = reinterpret_cast<float4*>(s_lut);
#pragma unroll
        for (int i = 0; i < (LUT_N * 2) / 4 / 256; ++i)    // 8 float4 per thread
            dst4[tid + i * 256] = src4[tid + i * 256];
    }
    __syncthreads();

    const float inv_dv = (float)(LUT_N - 1) / (LUT_VHI - LUT_VLO);
    const float off0   = -LUT_VLO * inv_dv;
    const float pmax   = (float)(LUT_N - 1);

    const int tx = threadIdx.x;                       // 0..31 (one warp per ty)
    const int c0 = (blockIdx.x * 32 + tx) * 4;
    const int b  = blockIdx.z;
    const int y0 = (blockIdx.y * blockDim.y + threadIdx.y) * T;

    const float* img  = in  + (size_t)b * (IMG_H * IMG_W);
    float*       oimg = out + (size_t)b * (IMG_H * IMG_W);

    float win[3][6];   // 3-row sliding window: [c0-1, c0..c0+3, c0+4]

    auto load_row = [&](int y, float* r) {
        if (y < 0 || y >= IMG_H) {
#pragma unroll
            for (int i = 0; i < 6; ++i) r[i] = 0.0f;
            return;
        }
        const float* p = img + y * IMG_W + c0;
        float4 v = *reinterpret_cast<const float4*>(p);
        // halos from neighbor lanes (warp spans a contiguous 128-col strip)
        float left  = __shfl_up_sync(0xffffffffu,  v.w, 1);
        float right = __shfl_down_sync(0xffffffffu, v.x, 1);
        if (tx == 0)  left  = (c0 > 0)           ? __ldg(p - 1) : 0.0f;
        if (tx == 31) right = (c0 + 4 < IMG_W)   ? __ldg(p + 4) : 0.0f;
        r[0] = left;
        r[1] = v.x; r[2] = v.y; r[3] = v.z; r[4] = v.w;
        r[5] = right;
    };

    load_row(y0 - 1, win[0]);
    load_row(y0,     win[1]);

#pragma unroll
    for (int t = 0; t < T; ++t) {
        const int y = y0 + t;
        float* rm = win[(t + 0) % 3];
        float* rc = win[(t + 1) % 3];
        float* rp = win[(t + 2) % 3];
        load_row(y + 1, rp);

        float res[4];
#pragma unroll
        for (int i = 0; i < 4; ++i) {
            float v;
            v = c_k[0] * rm[i];
            v = fmaf(c_k[1], rm[i + 1], v);
            v = fmaf(c_k[2], rm[i + 2], v);
            v = fmaf(c_k[3], rc[i],     v);
            v = fmaf(c_k[4], rc[i + 1], v);
            v = fmaf(c_k[5], rc[i + 2], v);
            v = fmaf(c_k[6], rp[i],     v);
            v = fmaf(c_k[7], rp[i + 1], v);
            v = fmaf(c_k[8], rp[i + 2], v);
            // single LDS.64 lookup + lerp (act constant outside [VLO,VHI])
            float pos = fminf(fmaxf(fmaf(v, inv_dv, off0), 0.0f), pmax);
            int   ip  = (int)pos;               // pos >= 0 -> trunc == floor
            float fr  = pos - (float)ip;
            float2 e  = s_lut[ip];
            res[i] = rc[i + 1] + fmaf(e.y, fr, e.x);
        }
        float4 o;
        o.x = res[0]; o.y = res[1]; o.z = res[2]; o.w = res[3];
        *reinterpret_cast<float4*>(oimg + y * IMG_W + c0) = o;
    }
}

extern "C" void kernel_launch(void* const* d_in, const int* in_sizes, int n_in,
                              void* d_out, int out_size) {
    const float* x  = (const float*)d_in[0];
    const float* k  = (const float*)d_in[1];
    const float* w1 = (const float*)d_in[2];
    const float* b1 = (const float*)d_in[3];
    const float* w2 = (const float*)d_in[4];
    float* out = (float*)d_out;

    const int npix  = in_sizes[0];
    const int B     = npix / (IMG_H * IMG_W);
    const int steps = out_size / npix - 1;

    cudaMemcpyToSymbolAsync(c_k, k, 9 * sizeof(float), 0, cudaMemcpyDeviceToDevice, 0);
    build_lut_kernel<<<LUT_N / 256, 256>>>(w1, b1, w2);

    cudaMemcpyAsync(out, x, (size_t)npix * sizeof(float), cudaMemcpyDeviceToDevice, 0);

    constexpr int T = 8;
    dim3 blk(32, 8, 1);
    dim3 grd(IMG_W / (32 * 4), IMG_H / (8 * T), B);   // (4, 8, B)

    for (int s = 0; s < steps; ++s) {
        const float* src = out + (size_t)s       * npix;
        float*       dst = out + (size_t)(s + 1) * npix;
        step_kernel<T><<<grd, blk>>>(src, dst);
    }
}